// round 3
// baseline (speedup 1.0000x reference)
#include <cuda_runtime.h>

// AEC frequency-domain dual-filter IPNLMS, round 3.
// 2 lanes/bin (taps 5+5). Latency-oriented: history-handoff SHFL pipelined one
// frame ahead, sliding-window reference power (exact refresh every 10 frames),
// gate applied post-clamp so A/B leave the critical path, single merged
// rare-path branch region. 9 blocks x 32 threads.

namespace {
constexpr int F_BINS   = 129;
constexpr int T_FRAMES = 2000;
constexpr int NF       = 16000;          // B*T, serial frame order (t, b)
constexpr int TF       = T_FRAMES * F_BINS;
}

__device__ __forceinline__ float pair_sum(float v) {
    return v + __shfl_xor_sync(0xffffffffu, v, 1);
}

__global__ void __launch_bounds__(32, 1)
aec_ipnlms3(const float* __restrict__ mic_r, const float* __restrict__ mic_i,
            const float* __restrict__ ref_r, const float* __restrict__ ref_i,
            const float* __restrict__ fir_r0, const float* __restrict__ fir_i0,
            const float* __restrict__ adf_r0, const float* __restrict__ adf_i0,
            float2* __restrict__ out)
{
    const float LAM = 0.97f;
    const float OML = (float)(1.0 - 0.97);   // match python double-derived constant

    const int lane = threadIdx.x;
    const int gid  = blockIdx.x * 32 + lane;
    const int bin  = gid >> 1;
    const int half = gid & 1;                 // 0: taps 0-4, 1: taps 5-9
    const bool writer = (half == 0) && (bin < F_BINS);
    const int f = (bin < F_BINS) ? bin : (F_BINS - 1);
    const bool low = (f <= 35);               // 10-tap window, else 8-tap
    const float m89   = low ? 1.0f : 0.0f;
    const float c0    = low ? 0.025f : 0.03125f;   // (1-ALPHA)/(2*nblocks)
    const float mtail = half ? m89 : 1.0f;    // mask on this lane's taps j=3,4

    // ---- register state ----
    float Hr[5], Hi[5], cfr[5], cfi[5], car[5], cai[5], mg2[5];
    float s_loc = 0.0f;
#pragma unroll
    for (int j = 0; j < 5; ++j) {
        const int k = half * 5 + j;
        const float mk = (k < 8) ? 1.0f : m89;   // zero masked taps (output-equivalent)
        Hr[j] = 0.0f; Hi[j] = 0.0f;
        cfr[j] = fir_r0[f * 10 + k] * mk;  cfi[j] = fir_i0[f * 10 + k] * mk;
        car[j] = adf_r0[f * 10 + k] * mk;  cai[j] = adf_i0[f * 10 + k] * mk;
        mg2[j] = car[j] * car[j] + cai[j] * cai[j];
        s_loc += mg2[j];
    }
    float s_sum  = pair_sum(s_loc);
    float invs15 = __fdividef(1.5f, s_sum + 1e-10f);
    float mse_in = 1.0f, mse_ad = 1.0f, mse_mn = 1.0f;
    float totv = 0.0f;                        // sliding masked Σ|h|² (refreshed at u==0)
    float sxr = 0.0f, sxi = 0.0f;             // pre-shuffled handoff for next insertion

    // ---- 2-deep prefetch pipeline ----
    float pmr[2], pmi[2], prr[2], pri[2];
    int poff[2] = { f, TF + f };
    pmr[0] = mic_r[poff[0]]; pmi[0] = mic_i[poff[0]];
    prr[0] = ref_r[poff[0]]; pri[0] = ref_i[poff[0]];
    pmr[1] = mic_r[poff[1]]; pmi[1] = mic_i[poff[1]];
    prr[1] = ref_r[poff[1]]; pri[1] = ref_i[poff[1]];

    for (int n0 = 0; n0 < NF; n0 += 10) {
#pragma unroll
        for (int u = 0; u < 10; ++u) {        // compile-time u
            const int n  = n0 + u;
            const int sl = u & 1;
            const float mr_f = pmr[sl], mi_f = pmi[sl];
            const float rr_f = prr[sl], ri_f = pri[sl];
            const int ooff = poff[sl];

            // compile-time slot indices
            const int ins  = (10 - u) % 5;            // insertion slot (frame n)
            const int ins2 = (9  - u) % 5;            // insertion slot (frame n+1)
            const int shi  = ((3 - u) % 5 + 5) % 5;   // old global tap7 (lane1 j=2)

            // ---- sliding-tot deltas (read leaving tap BEFORE insertion) ----
            float d;
            if (u != 0) {
                const float vor = low ? Hr[ins] : Hr[shi];
                const float voi = low ? Hi[ins] : Hi[shi];
                d = half ? -(vor * vor + voi * voi) : (rr_f * rr_f + ri_f * ri_f);
            }

            // ---- insert new tap (handoff pre-shuffled last frame) ----
            Hr[ins] = half ? sxr : rr_f;
            Hi[ins] = half ? sxi : ri_f;

            // ---- issue NEXT frame's handoff shuffle now (content is final) ----
            sxr = __shfl_xor_sync(0xffffffffu, Hr[ins2], 1);
            sxi = __shfl_xor_sync(0xffffffffu, Hi[ins2], 1);

            // ---- tot: sliding update, exact refresh every 10th frame ----
            if (u == 0) {
                float tl = 0.f, tt = 0.f;
#pragma unroll
                for (int j = 0; j < 5; ++j) {
                    const int p = ((j - u) % 5 + 5) % 5;
                    const float v = Hr[p] * Hr[p] + Hi[p] * Hi[p];
                    if (j < 3) tl += v; else tt += v;
                }
                tl += mtail * tt;
                totv = pair_sum(tl);
            } else {
                const float dx = __shfl_xor_sync(0xffffffffu, d, 1);
                totv = totv + (d + dx);
            }

            // ---- A/B (no gate): off the critical path ----
            const float mu_n = __fdividef(0.5f, (totv + 1e-8f) + 1e-10f);
            const float A  = mu_n * c0;
            const float B  = mu_n * invs15;
            const float At = A * mtail;
            const float Bt = B * mtail;

            // ---- prefetch frame n+2 (branchless) ----
            {
                const int n2 = (n + 2 < NF) ? (n + 2) : (NF - 1);
                const int off = (n2 & 7) * TF + (n2 >> 3) * F_BINS + f;
                poff[sl] = off;
                pmr[sl] = __ldg(mic_r + off); pmi[sl] = __ldg(mic_i + off);
                prr[sl] = __ldg(ref_r + off); pri[sl] = __ldg(ref_i + off);
            }

            // ---- dual-filter echo estimates ----
            float fer = 0.f, fei = 0.f, aer = 0.f, aei = 0.f;
#pragma unroll
            for (int j = 0; j < 5; ++j) {
                const int p = ((j - u) % 5 + 5) % 5;
                const float hr = Hr[p], hi = Hi[p];
                fer += cfr[j] * hr + cfi[j] * hi;
                fei += cfr[j] * hi - cfi[j] * hr;
                aer += car[j] * hr + cai[j] * hi;
                aei += car[j] * hi - cai[j] * hr;
            }
            fer = pair_sum(fer); fei = pair_sum(fei);
            aer = pair_sum(aer); aei = pair_sum(aei);

            const float feR = mr_f - fer, feI = mi_f - fei;
            const float aeR = mr_f - aer, aeI = mi_f - aei;
            const float f_pow = feR * feR + feI * feI;
            const float a_pow = aeR * aeR + aeI * aeI;
            const bool selA = (f_pow >= a_pow);
            const float errR = selA ? aeR : feR;
            const float errI = selA ? aeI : feI;

            // ---- MSE smoothing + control ----
            mse_in = LAM * mse_in + OML * (mr_f * mr_f + mi_f * mi_f);
            mse_mn = LAM * mse_mn + OML * f_pow;
            mse_ad = LAM * mse_ad + OML * a_pow;
            const float gate = (mse_ad > mse_in * 8.0f) ? 0.0f : 1.0f;
            const bool rec = (mse_in > mse_mn * 8.0f) && (mse_mn < 0.5f * mse_ad);

            // ---- IPNLMS update (gate post-clamp: gate∈{0,1} commutes with clip) ----
            float s_new = 0.f;
#pragma unroll
            for (int j = 0; j < 5; ++j) {
                const int p = ((j - u) % 5 + 5) % 5;
                const float hr = Hr[p], hi = Hi[p];
                const float g2 = (j >= 3) ? (At + mg2[j] * Bt) : (A + mg2[j] * B);
                const float p_r = hr * aeR + hi * aeI;
                const float p_i = hi * aeR - hr * aeI;
                const float ur = fminf(fmaxf(g2 * p_r, -0.01f), 0.01f);
                const float ui = fminf(fmaxf(g2 * p_i, -0.01f), 0.01f);
                car[j] = fmaf(ur, gate, car[j]);
                cai[j] = fmaf(ui, gate, cai[j]);
                mg2[j] = car[j] * car[j] + cai[j] * cai[j];
                s_new += mg2[j];
            }
            float s_tot = pair_sum(s_new);

            // ---- single merged rare-path region (renorm + recovery) ----
            if (__any_sync(0xffffffffu, (s_tot >= 4.0f) || rec)) {
                // MAX_COEF renorm (s_tot<4 on all lanes => all scales exactly 1)
#pragma unroll
                for (int j = 0; j < 5; ++j) {
                    const float mg = sqrtf(mg2[j] + 1e-10f);
                    const float sc = (mg > 2.0f) ? (2.0f / mg) : 1.0f;
                    car[j] *= sc; cai[j] *= sc;
                }
                // copy adaptive -> main where adaptive won
#pragma unroll
                for (int j = 0; j < 5; ++j) {
                    cfr[j] = selA ? car[j] : cfr[j];
                    cfi[j] = selA ? cai[j] : cfi[j];
                }
                // recovery: reload adaptive from main
                float s2 = 0.f;
#pragma unroll
                for (int j = 0; j < 5; ++j) {
                    car[j] = rec ? cfr[j] : car[j];
                    cai[j] = rec ? cfi[j] : cai[j];
                    mg2[j] = car[j] * car[j] + cai[j] * cai[j];
                    s2 += mg2[j];
                }
                s_tot = pair_sum(s2);
            } else {
#pragma unroll
                for (int j = 0; j < 5; ++j) {
                    cfr[j] = selA ? car[j] : cfr[j];
                    cfi[j] = selA ? cai[j] : cfi[j];
                }
            }
            s_sum  = s_tot;
            invs15 = __fdividef(1.5f, s_sum + 1e-10f);   // for next frame's B

            // ---- NLP every 10th frame (compile-time) ----
            float o_r = errR, o_i = errI;
            if (u == 0) {
                const float echR = selA ? aer : fer;
                const float echI = selA ? aei : fei;
                const float em = sqrtf(errR * errR + errI * errI + 1e-12f);
                const float cm = sqrtf(echR * echR + echI * echI);
                const float supp = fmaxf(em - 1.5f * cm, 0.01f * em);
                const float g = supp / em;
                o_r = g * errR; o_i = g * errI;
            }

            if (writer) out[ooff] = make_float2(o_r, o_i);
        }
    }
}

extern "C" void kernel_launch(void* const* d_in, const int* in_sizes, int n_in,
                              void* d_out, int out_size) {
    (void)in_sizes; (void)n_in; (void)out_size;
    aec_ipnlms3<<<9, 32>>>(
        (const float*)d_in[0], (const float*)d_in[1],
        (const float*)d_in[2], (const float*)d_in[3],
        (const float*)d_in[4], (const float*)d_in[5],
        (const float*)d_in[6], (const float*)d_in[7],
        (float2*)d_out);
}